// round 1
// baseline (speedup 1.0000x reference)
#include <cuda_runtime.h>
#include <cstdint>

// GridCellRouter: H=W=4096, N=16,777,216 cells, 16 iterations.
//   accum = scatter_add(accum, flow_idx, cur)
//   cur   = accum - cur
// Output: accum after 16 iterations.

#define N_CELLS (4096 * 4096)
#define ITERS 16

// 64 MB scratch for `cur` (allocation-free: __device__ global).
__device__ float g_cur[N_CELLS];

// ---- streaming load/store helpers (evict-first in L2 so accum stays hot) ----
__device__ __forceinline__ float4 ldcs_f4(const float4* p) {
    float4 v;
    asm volatile("ld.global.cs.v4.f32 {%0,%1,%2,%3}, [%4];"
                 : "=f"(v.x), "=f"(v.y), "=f"(v.z), "=f"(v.w) : "l"(p));
    return v;
}
__device__ __forceinline__ int4 ldcs_i4(const int4* p) {
    int4 v;
    asm volatile("ld.global.cs.v4.b32 {%0,%1,%2,%3}, [%4];"
                 : "=r"(v.x), "=r"(v.y), "=r"(v.z), "=r"(v.w) : "l"(p));
    return v;
}
__device__ __forceinline__ void stcs_f4(float4* p, float4 v) {
    asm volatile("st.global.cs.v4.f32 [%0], {%1,%2,%3,%4};"
                 :: "l"(p), "f"(v.x), "f"(v.y), "f"(v.z), "f"(v.w) : "memory");
}

// Init: accum = runoff (d_out is poisoned, must be written).
__global__ void init_kernel(const float4* __restrict__ runoff, float4* __restrict__ accum, int n4) {
    int i = blockIdx.x * blockDim.x + threadIdx.x;
    if (i < n4) accum[i] = runoff[i];
}

// Phase 1: atomicAdd(accum[idx[i]], cur[i]) for all i. Vectorized x4.
__global__ void scatter_kernel(const float* __restrict__ cur,
                               const int* __restrict__ idx,
                               float* __restrict__ accum, int n4) {
    int t = blockIdx.x * blockDim.x + threadIdx.x;
    if (t >= n4) return;
    float4 c = ldcs_f4(reinterpret_cast<const float4*>(cur) + t);
    int4 d = ldcs_i4(reinterpret_cast<const int4*>(idx) + t);
    atomicAdd(accum + d.x, c.x);   // return value unused -> RED.E.ADD.F32
    atomicAdd(accum + d.y, c.y);
    atomicAdd(accum + d.z, c.z);
    atomicAdd(accum + d.w, c.w);
}

// Phase 2: cur_out[i] = accum[i] - cur_in[i]. Vectorized x4.
__global__ void update_kernel(const float4* __restrict__ accum,
                              const float* __restrict__ cur_in,
                              float* __restrict__ cur_out, int n4) {
    int t = blockIdx.x * blockDim.x + threadIdx.x;
    if (t >= n4) return;
    float4 a = accum[t];  // want L2 hits here (accum is hot from scatter)
    float4 c = ldcs_f4(reinterpret_cast<const float4*>(cur_in) + t);
    float4 o;
    o.x = a.x - c.x; o.y = a.y - c.y; o.z = a.z - c.z; o.w = a.w - c.w;
    stcs_f4(reinterpret_cast<float4*>(cur_out) + t, o);
}

extern "C" void kernel_launch(void* const* d_in, const int* in_sizes, int n_in,
                              void* d_out, int out_size) {
    const float* runoff = (const float*)d_in[0];
    const int* flow_idx = (const int*)d_in[1];
    float* accum = (float*)d_out;

    float* cur = nullptr;
    cudaGetSymbolAddress((void**)&cur, g_cur);

    const int n4 = N_CELLS / 4;             // 4,194,304
    const int threads = 256;
    const int blocks = (n4 + threads - 1) / threads;  // 16,384

    init_kernel<<<blocks, threads>>>((const float4*)runoff, (float4*)accum, n4);

    const float* cur_src = runoff;          // iteration 1 reads runoff directly
    for (int it = 0; it < ITERS; ++it) {
        scatter_kernel<<<blocks, threads>>>(cur_src, flow_idx, accum, n4);
        update_kernel<<<blocks, threads>>>((const float4*)accum, cur_src, cur, n4);
        cur_src = cur;
    }
}